// round 16
// baseline (speedup 1.0000x reference)
#include <cuda_runtime.h>
#include <math.h>

// Fixed problem shape
#define BB 16
#define HH 544
#define WW 960
#define NTOT (BB * HH * WW)              // 8,355,840
#define THREADS 256
#define ITEMS 8
#define BLOCK_PX 1024                    // pixels per block-item (4 px/thread)
#define GRID (NTOT / (BLOCK_PX * ITEMS)) // 1020 blocks (exact)
#define ISTRIDE (GRID * BLOCK_PX)        // 1,044,480 pixels between items

// Global accumulators: [0]=count, [1]=sum sl1(dl-dlgt)*m, [2]=sum sl1(recon-lgt)*m
__device__ double   g_acc[3];
__device__ unsigned g_done;

__device__ __forceinline__ float smooth_l1(float d) {
    float ad = fabsf(d);
    return (ad < 1.0f) ? 0.5f * ad * ad : ad - 0.5f;
}

__global__ void __launch_bounds__(THREADS, 7)
fused_loss_kernel(const float* __restrict__ dl,
                  const float* __restrict__ seg,
                  const float* __restrict__ dlgt,
                  const float* __restrict__ lgt,
                  float* __restrict__ out)
{
    const int tid  = threadIdx.x;
    const int lane = tid & 31;
    const int wid  = tid >> 5;
    // lane-contiguous mapping: warp owns 128 consecutive pixels; k-group g has
    // lanes at consecutive addresses (gather span = 32 cols + 64 disp ~ 3.5 lines
    // instead of 7 with float4 lane-spacing-4 layout).
    const int toff = wid * 128 + lane;

    float cnt = 0.0f, sd = 0.0f, sr = 0.0f;

    int pbase = blockIdx.x * BLOCK_PX + toff;

    // ---- depth-1 pipeline prologue: 12 independent scalar loads ----
    float dvc[4], lvc[4], gvc[4];
    #pragma unroll
    for (int k = 0; k < 4; k++) {
        const int p = pbase + k * 32;
        dvc[k] = __ldcs(dl   + p);
        lvc[k] = __ldcs(lgt  + p);
        gvc[k] = __ldcs(dlgt + p);
    }

    #pragma unroll
    for (int it = 0; it < ITEMS; it++) {
        // prefetch next item's 12 scalars while computing this one
        float dvn[4], lvn[4], gvn[4];
        const int pnext = pbase + ISTRIDE;
        if (it + 1 < ITEMS) {
            #pragma unroll
            for (int k = 0; k < 4; k++) {
                const int p = pnext + k * 32;
                dvn[k] = __ldcs(dl   + p);
                lvn[k] = __ldcs(lgt  + p);
                gvn[k] = __ldcs(dlgt + p);
            }
        }

        #pragma unroll
        for (int k = 0; k < 4; k++) {
            const int p   = pbase + k * 32;
            const int row = p / WW;               // const-div -> mul-hi
            const int col = p - row * WW;
            const float* __restrict__ s = seg + row * WW;

            const float d  = dvc[k];
            const float l  = lvc[k];
            const float dg = gvc[k];
            const bool  msk = (l > 0.0f);

            const float t0 = smooth_l1(d - dg);

            // horizontal bilinear warp at (col - d), zeros padding
            const float sx  = (float)col - d;
            const float x0f = floorf(sx);
            const float wx  = sx - x0f;
            const int   x0i = (int)x0f;
            const int   x1i = x0i + 1;
            // d >= 0 -> x0i <= col < W: only lower bound needed for g0
            const float g0 = (msk & (x0i >= 0))                     ? __ldg(s + x0i) : 0.0f;
            const float g1 = (msk & ((unsigned)x1i < (unsigned)WW)) ? __ldg(s + x1i) : 0.0f;
            const float warped = (1.0f - wx) * g0 + wx * g1;

            const float recon = __fdividef(1.0f, 1.0f + __expf(-warped));
            const float t1 = smooth_l1(recon - l);

            if (msk) {
                cnt += 1.0f;
                sd  += t0;
                sr  += t1;
            }
        }

        #pragma unroll
        for (int k = 0; k < 4; k++) { dvc[k] = dvn[k]; lvc[k] = lvn[k]; gvc[k] = gvn[k]; }
        pbase = pnext;
    }

    // ---- Block reduction: warp shuffles -> shared -> fp64 atomics ----
    #pragma unroll
    for (int off = 16; off > 0; off >>= 1) {
        cnt += __shfl_down_sync(0xffffffffu, cnt, off);
        sd  += __shfl_down_sync(0xffffffffu, sd,  off);
        sr  += __shfl_down_sync(0xffffffffu, sr,  off);
    }

    __shared__ float s_cnt[THREADS / 32];
    __shared__ float s_sd [THREADS / 32];
    __shared__ float s_sr [THREADS / 32];

    if (lane == 0) { s_cnt[wid] = cnt; s_sd[wid] = sd; s_sr[wid] = sr; }
    __syncthreads();

    if (wid == 0) {
        cnt = (lane < THREADS / 32) ? s_cnt[lane] : 0.0f;
        sd  = (lane < THREADS / 32) ? s_sd [lane] : 0.0f;
        sr  = (lane < THREADS / 32) ? s_sr [lane] : 0.0f;
        #pragma unroll
        for (int off = 4; off > 0; off >>= 1) {
            cnt += __shfl_down_sync(0xffffffffu, cnt, off);
            sd  += __shfl_down_sync(0xffffffffu, sd,  off);
            sr  += __shfl_down_sync(0xffffffffu, sr,  off);
        }
        if (lane == 0) {
            atomicAdd(&g_acc[0], (double)cnt);
            atomicAdd(&g_acc[1], (double)sd);
            atomicAdd(&g_acc[2], (double)sr);

            // ---- Last-block finalize (fused) ----
            __threadfence();
            const unsigned ticket = atomicAdd(&g_done, 1u);
            if (ticket == GRID - 1) {
                const double tc = g_acc[0];
                const double ts = g_acc[1];
                const double tr = g_acc[2];

                float loss = (float)(ts / tc);
                if (isnan(loss)) loss = 0.0f;
                const float loss_recon = (float)(tr / tc);
                out[0] = loss + 0.5f * loss_recon;

                g_acc[0] = 0.0;
                g_acc[1] = 0.0;
                g_acc[2] = 0.0;
                g_done   = 0u;
            }
        }
    }
}

extern "C" void kernel_launch(void* const* d_in, const int* in_sizes, int n_in,
                              void* d_out, int out_size)
{
    const float* dl   = (const float*)d_in[0];
    const float* seg  = (const float*)d_in[1];
    const float* dlgt = (const float*)d_in[2];
    const float* lgt  = (const float*)d_in[3];
    float* out = (float*)d_out;

    fused_loss_kernel<<<GRID, THREADS>>>(dl, seg, dlgt, lgt, out);
}

// round 17
// speedup vs baseline: 1.2064x; 1.2064x over previous
#include <cuda_runtime.h>
#include <math.h>

// Fixed problem shape
#define BB 16
#define HH 544
#define WW 960
#define NTOT (BB * HH * WW)              // 8,355,840
#define N4   (NTOT / 4)                  // 2,088,960 float4 chunks
#define THREADS 256
#define ITEMS 8
#define GRID (N4 / (THREADS * ITEMS))    // 1020 blocks (exact; single wave)
#define STRIDE (GRID * THREADS)          // 261,120 float4s between items

// Global accumulators: [0]=count, [1]=sum sl1(dl-dlgt)*m, [2]=sum sl1(recon-lgt)*m
__device__ double   g_acc[3];
__device__ unsigned g_done;

__device__ __forceinline__ float smooth_l1(float d) {
    float ad = fabsf(d);
    return (ad < 1.0f) ? 0.5f * ad * ad : ad - 0.5f;
}

// Keep a loaded value alive without emitting any instruction: forces the
// coalesced seg "warming" load to actually retire (unlike prefetch.global.L2,
// which can be silently dropped under LSU queue pressure).
__device__ __forceinline__ void keep_alive(float4& v) {
    asm volatile("" : "+f"(v.x), "+f"(v.y), "+f"(v.z), "+f"(v.w));
}

__global__ void __launch_bounds__(THREADS, 7)
fused_loss_kernel(const float* __restrict__ dl,
                  const float* __restrict__ seg,
                  const float* __restrict__ dlgt,
                  const float* __restrict__ lgt,
                  float* __restrict__ out)
{
    const int tid = threadIdx.x;
    const float4* __restrict__ dl4 = reinterpret_cast<const float4*>(dl);
    const float4* __restrict__ lg4 = reinterpret_cast<const float4*>(lgt);
    const float4* __restrict__ gt4 = reinterpret_cast<const float4*>(dlgt);
    const float4* __restrict__ sg4 = reinterpret_cast<const float4*>(seg);

    float cnt = 0.0f, sd = 0.0f, sr = 0.0f;

    int i4 = blockIdx.x * THREADS + tid;

    // ---- depth-1 prologue: 3 streams to registers + seg warming load ----
    float4 dv = __ldcs(dl4 + i4);
    float4 lv = __ldcs(lg4 + i4);
    float4 gv = __ldcs(gt4 + i4);
    float4 sv = __ldg (sg4 + i4);        // populates L1/L2 for item 0's gathers

    #pragma unroll
    for (int it = 0; it < ITEMS; it++) {
        // prefetch next item (3 streams + seg warm) while computing this one
        float4 dvn, lvn, gvn, svn;
        const int inext = i4 + STRIDE;
        if (it + 1 < ITEMS) {
            dvn = __ldcs(dl4 + inext);
            lvn = __ldcs(lg4 + inext);
            gvn = __ldcs(gt4 + inext);
            svn = __ldg (sg4 + inext);   // warm L1/L2 one iteration ahead
        }

        // retire the warming load for the CURRENT item (no instruction emitted);
        // by now it has long since arrived, so no stall.
        keep_alive(sv);

        const int idx = i4 * 4;
        const int row = idx / WW;                 // const-div -> mul-hi
        const int wb  = idx - row * WW;
        const float* __restrict__ s = seg + row * WW;
        const float wf = (float)wb;

        #pragma unroll
        for (int k = 0; k < 4; k++) {
            const float d  = (&dv.x)[k];
            const float l  = (&lv.x)[k];
            const float dg = (&gv.x)[k];
            const bool  msk = (l > 0.0f);

            const float t0 = smooth_l1(d - dg);

            // horizontal bilinear warp at (w - d), zeros padding.
            // gathers now hit L1/L2 thanks to the warming stream.
            const float sx  = (wf + (float)k) - d;
            const float x0f = floorf(sx);
            const float wx  = sx - x0f;
            const int   x0i = (int)x0f;
            const int   x1i = x0i + 1;
            // d >= 0 -> x0i <= w < W: only lower bound needed for g0
            const float g0 = (msk & (x0i >= 0))                     ? __ldg(s + x0i) : 0.0f;
            const float g1 = (msk & ((unsigned)x1i < (unsigned)WW)) ? __ldg(s + x1i) : 0.0f;
            const float warped = (1.0f - wx) * g0 + wx * g1;

            // sigmoid via fast exp + fast reciprocal
            const float recon = __fdividef(1.0f, 1.0f + __expf(-warped));
            const float t1 = smooth_l1(recon - l);

            if (msk) {
                cnt += 1.0f;
                sd  += t0;
                sr  += t1;
            }
        }

        dv = dvn; lv = lvn; gv = gvn; sv = svn;
        i4 = inext;
    }

    // ---- Block reduction: warp shuffles -> shared -> fp64 atomics ----
    #pragma unroll
    for (int off = 16; off > 0; off >>= 1) {
        cnt += __shfl_down_sync(0xffffffffu, cnt, off);
        sd  += __shfl_down_sync(0xffffffffu, sd,  off);
        sr  += __shfl_down_sync(0xffffffffu, sr,  off);
    }

    __shared__ float s_cnt[THREADS / 32];
    __shared__ float s_sd [THREADS / 32];
    __shared__ float s_sr [THREADS / 32];

    const int lane = tid & 31;
    const int wid  = tid >> 5;
    if (lane == 0) { s_cnt[wid] = cnt; s_sd[wid] = sd; s_sr[wid] = sr; }
    __syncthreads();

    if (wid == 0) {
        cnt = (lane < THREADS / 32) ? s_cnt[lane] : 0.0f;
        sd  = (lane < THREADS / 32) ? s_sd [lane] : 0.0f;
        sr  = (lane < THREADS / 32) ? s_sr [lane] : 0.0f;
        #pragma unroll
        for (int off = 4; off > 0; off >>= 1) {
            cnt += __shfl_down_sync(0xffffffffu, cnt, off);
            sd  += __shfl_down_sync(0xffffffffu, sd,  off);
            sr  += __shfl_down_sync(0xffffffffu, sr,  off);
        }
        if (lane == 0) {
            atomicAdd(&g_acc[0], (double)cnt);
            atomicAdd(&g_acc[1], (double)sd);
            atomicAdd(&g_acc[2], (double)sr);

            // ---- Last-block finalize (fused) ----
            __threadfence();
            const unsigned ticket = atomicAdd(&g_done, 1u);
            if (ticket == GRID - 1) {
                const double tc = g_acc[0];
                const double ts = g_acc[1];
                const double tr = g_acc[2];

                float loss = (float)(ts / tc);
                if (isnan(loss)) loss = 0.0f;
                const float loss_recon = (float)(tr / tc);
                out[0] = loss + 0.5f * loss_recon;

                g_acc[0] = 0.0;
                g_acc[1] = 0.0;
                g_acc[2] = 0.0;
                g_done   = 0u;
            }
        }
    }
}

extern "C" void kernel_launch(void* const* d_in, const int* in_sizes, int n_in,
                              void* d_out, int out_size)
{
    const float* dl   = (const float*)d_in[0];
    const float* seg  = (const float*)d_in[1];
    const float* dlgt = (const float*)d_in[2];
    const float* lgt  = (const float*)d_in[3];
    float* out = (float*)d_out;

    fused_loss_kernel<<<GRID, THREADS>>>(dl, seg, dlgt, lgt, out);
}